// round 13
// baseline (speedup 1.0000x reference)
#include <cuda_runtime.h>
#include <cuda_fp16.h>
#include <cstdint>

#define NN 50000
#define EE 800000
#define CIN 256
#define HD  256   // H*D
#define DD  64
#define HH  4

// ---------------- device scratch ----------------
__device__ __half g_xh[(size_t)NN * CIN];    // x in fp16
__device__ __half g_wh[768 * 256];           // [outcol][k]  (B^T layout), fp16
__device__ float g_bvo[256];
__device__ __half g_qh[(size_t)NN * HD];     // q in fp16
__device__ __half g_kh[(size_t)NN * HD];     // k in fp16
__device__ float g_u[(size_t)NN * HD];       // u = x @ (Wv@Wo per head) + bvo
__device__ float g_acc[NN * HH];
__device__ float g_hsum[HH];

__device__ __forceinline__ uint32_t smem_u32(const void* p) {
    uint32_t a;
    asm("{ .reg .u64 t; cvta.to.shared.u64 t, %1; cvt.u32.u64 %0, t; }" : "=r"(a) : "l"(p));
    return a;
}
__device__ __forceinline__ void ldmatrix_x4(uint32_t& r0, uint32_t& r1, uint32_t& r2, uint32_t& r3, uint32_t addr) {
    asm volatile("ldmatrix.sync.aligned.m8n8.x4.shared.b16 {%0,%1,%2,%3}, [%4];"
        : "=r"(r0), "=r"(r1), "=r"(r2), "=r"(r3) : "r"(addr));
}
__device__ __forceinline__ void cp_async16(uint32_t smem_addr, const void* gptr) {
    asm volatile("cp.async.cg.shared.global [%0], [%1], 16;" :: "r"(smem_addr), "l"(gptr));
}
#define CP_COMMIT() asm volatile("cp.async.commit_group;" ::: "memory")
#define CP_WAIT(n)  asm volatile("cp.async.wait_group %0;" :: "n"(n) : "memory")

// ---------------- K0a: x -> fp16 ----------------
__global__ __launch_bounds__(256) void conv_x_k(const float* __restrict__ x) {
    size_t g = (size_t)blockIdx.x * 256 + threadIdx.x;   // float4 index
    float4 v = ((const float4*)x)[g];
    __half2* ph = (__half2*)g_xh;
    ph[g * 2]     = __floats2half2_rn(v.x, v.y);
    ph[g * 2 + 1] = __floats2half2_rn(v.z, v.w);
}

// ---------------- K0b: combined weight [Wq|Wk|Wvo], transposed, fp16 ----------------
__global__ __launch_bounds__(768) void conv_w_k(
    const float* __restrict__ Wq, const float* __restrict__ Wk,
    const float* __restrict__ Wv, const float* __restrict__ Wo,
    const float* __restrict__ bv)
{
    __shared__ float sWv[256];
    const int c = blockIdx.x;          // k index 0..255
    const int t = threadIdx.x;         // output col 0..767
    if (t < 256) sWv[t] = Wv[c * 256 + t];
    __syncthreads();
    float w;
    if (t < 256)       w = Wq[c * 256 + t];
    else if (t < 512)  w = Wk[c * 256 + (t - 256)];
    else {
        int i = t - 512, h = i >> 6, d = i & 63;
        float s = 0.f;
        #pragma unroll 8
        for (int j = 0; j < 64; j++) s += sWv[h * 64 + j] * Wo[(h * 64 + j) * 64 + d];
        w = s;
    }
    g_wh[t * 256 + c] = __float2half_rn(w);
    if (c == 0 && t >= 512) {
        int i = t - 512, h = i >> 6, d = i & 63;
        float s = 0.f;
        for (int j = 0; j < 64; j++) s += bv[h * 64 + j] * Wo[(h * 64 + j) * 64 + d];
        g_bvo[i] = s;
    }
}

// ---------------- K0c: zero accumulators ----------------
__global__ void init_k() {
    int i = blockIdx.x * blockDim.x + threadIdx.x;
    if (i < NN * HH) g_acc[i] = 0.f;
    if (i < HH)      g_hsum[i] = 0.f;
}

// ---------------- K1: single-pass fp16 HMMA GEMM [50048 x 256] @ [256 x 768] ----------------
// Block 128x128, 8 warps (warp tile 32x64), k-chunk 64 (4 chunks), 3-stage cp.async pipeline.
// XOR-swizzled smem: phys(row, unit16) = row*128B + (unit ^ (row&7))*16B.
#define STAGE_BYTES 16384
#define SMEM_TOTAL  (6 * STAGE_BYTES)        // A x3 stages, B x3 stages = 96 KB

__device__ __forceinline__ void mma_fp16(float* c, const uint32_t* a, const uint32_t* b) {
    asm volatile("mma.sync.aligned.m16n8k16.row.col.f32.f16.f16.f32 "
        "{%0,%1,%2,%3}, {%4,%5,%6,%7}, {%8,%9}, {%0,%1,%2,%3};"
        : "+f"(c[0]), "+f"(c[1]), "+f"(c[2]), "+f"(c[3])
        : "r"(a[0]), "r"(a[1]), "r"(a[2]), "r"(a[3]), "r"(b[0]), "r"(b[1]));
}

__global__ __launch_bounds__(256, 2) void gemm_mma(
    const float* __restrict__ bq, const float* __restrict__ bk)
{
    extern __shared__ __align__(16) char smem[];
    const uint32_t base = smem_u32(smem);
    const uint32_t aBase = base;                       // stage s at +s*STAGE_BYTES
    const uint32_t bBase = base + 3 * STAGE_BYTES;     // stage s at +s*STAGE_BYTES

    const int t = threadIdx.x, wid = t >> 5, lane = t & 31;
    const int gr = lane >> 2, q4 = lane & 3;
    const int rowBase = blockIdx.y * 128;
    const int col0 = blockIdx.x * 128;
    const int m0 = (wid >> 1) * 32, n0 = (wid & 1) * 64;

    // ---- cp.async indexing: thread t copies 4 x 16B for A and for B per chunk
    const int lrow = t >> 1;             // 0..127
    const int lq   = (t & 1) * 4;        // first unit (0 or 4)
    const int xr   = lrow & 7;           // store swizzle
    const int growA = (rowBase + lrow < NN) ? rowBase + lrow : NN - 1;  // clamp; rows>=NN never stored
    const __half* gA = g_xh + (size_t)growA * 256;
    const __half* gB = g_wh + (size_t)(col0 + lrow) * 256;
    const uint32_t sAr = aBase + (uint32_t)lrow * 128;
    const uint32_t sBr = bBase + (uint32_t)lrow * 128;
    uint32_t stU[4];
    #pragma unroll
    for (int i = 0; i < 4; i++) stU[i] = (uint32_t)(((lq + i) ^ xr) << 4);

    // ---- ldmatrix row-base addresses (stage + swizzle unit added per k-step)
    const int arow = (lane & 15);
    const int brow = (lane & 7) + ((lane >> 4) & 1) * 8;
    const uint32_t lx7 = (uint32_t)(lane & 7);
    const uint32_t uAbit = (uint32_t)(lane >> 4);          // A: unit lsb
    const uint32_t uBbit = (uint32_t)((lane >> 3) & 1);    // B: unit lsb
    uint32_t addrA[2], addrB[4];
    #pragma unroll
    for (int f = 0; f < 2; f++)
        addrA[f] = aBase + (uint32_t)(m0 + f * 16 + arow) * 128;
    #pragma unroll
    for (int gp = 0; gp < 4; gp++)
        addrB[gp] = bBase + (uint32_t)(n0 + gp * 16 + brow) * 128;

    float C[2][8][4] = {};

    // prologue: chunk 0 -> stage 0, chunk 1 -> stage 1
    #pragma unroll
    for (int i = 0; i < 4; i++) {
        cp_async16(sAr + stU[i], gA + (lq + i) * 8);
        cp_async16(sBr + stU[i], gB + (lq + i) * 8);
    }
    CP_COMMIT();
    #pragma unroll
    for (int i = 0; i < 4; i++) {
        cp_async16(sAr + STAGE_BYTES + stU[i], gA + 64 + (lq + i) * 8);
        cp_async16(sBr + STAGE_BYTES + stU[i], gB + 64 + (lq + i) * 8);
    }
    CP_COMMIT();

    #pragma unroll
    for (int kc = 0; kc < 4; kc++) {
        const uint32_t sOff = (uint32_t)(kc % 3) * STAGE_BYTES;
        if (kc < 2) {
            // stage (kc+2)%3 is free: its compute (chunk kc-1) finished before last sync
            const uint32_t nOff = (uint32_t)((kc + 2) % 3) * STAGE_BYTES;
            const int kt = (kc + 2) * 64;
            #pragma unroll
            for (int i = 0; i < 4; i++) {
                cp_async16(sAr + nOff + stU[i], gA + kt + (lq + i) * 8);
                cp_async16(sBr + nOff + stU[i], gB + kt + (lq + i) * 8);
            }
            CP_COMMIT();
            CP_WAIT(2);
        } else if (kc == 2) {
            CP_WAIT(1);
        } else {
            CP_WAIT(0);
        }
        __syncthreads();

        #pragma unroll
        for (int s = 0; s < 4; s++) {
            const uint32_t uA = ((((uint32_t)s << 1) | uAbit) ^ lx7) << 4;
            const uint32_t uB = ((((uint32_t)s << 1) | uBbit) ^ lx7) << 4;
            uint32_t a[2][4], b[8][2];
            #pragma unroll
            for (int f = 0; f < 2; f++)
                ldmatrix_x4(a[f][0], a[f][1], a[f][2], a[f][3], addrA[f] + sOff + uA);
            #pragma unroll
            for (int gp = 0; gp < 4; gp++)
                ldmatrix_x4(b[2 * gp][0], b[2 * gp][1], b[2 * gp + 1][0], b[2 * gp + 1][1],
                            addrB[gp] + sOff + uB);
            #pragma unroll
            for (int f = 0; f < 2; f++)
                #pragma unroll
                for (int g = 0; g < 8; g++)
                    mma_fp16(C[f][g], a[f], b[g]);
        }
        __syncthreads();
    }

    // epilogue: bias; q,k -> fp16, u -> fp32
    const int which = col0 >> 8;
    const int wcol0 = col0 & 255;

    #pragma unroll
    for (int f = 0; f < 2; f++) {
        int r0 = rowBase + m0 + f * 16 + gr;
        #pragma unroll
        for (int g = 0; g < 8; g++) {
            int c = wcol0 + n0 + g * 8 + q4 * 2;
            if (which < 2) {
                const float* bias = (which == 0) ? bq : bk;
                __half* OUT = (which == 0) ? g_qh : g_kh;
                float b0 = bias[c], b1 = bias[c + 1];
                if (r0 < NN)
                    *(__half2*)&OUT[(size_t)r0 * 256 + c] =
                        __floats2half2_rn(C[f][g][0] + b0, C[f][g][1] + b1);
                if (r0 + 8 < NN)
                    *(__half2*)&OUT[(size_t)(r0 + 8) * 256 + c] =
                        __floats2half2_rn(C[f][g][2] + b0, C[f][g][3] + b1);
            } else {
                float b0 = g_bvo[c], b1 = g_bvo[c + 1];
                if (r0 < NN)
                    *(float2*)&g_u[(size_t)r0 * 256 + c] =
                        make_float2(C[f][g][0] + b0, C[f][g][1] + b1);
                if (r0 + 8 < NN)
                    *(float2*)&g_u[(size_t)(r0 + 8) * 256 + c] =
                        make_float2(C[f][g][2] + b0, C[f][g][3] + b1);
            }
        }
    }
}

// ---------------- K2: per-edge scores -> exp -> scalar scatter-add ----------------
// 4 edges per warp iteration (8 independent 16B gathers in flight); persistent grid.
__global__ __launch_bounds__(256) void edge_k(
    const int* __restrict__ ei,
    const float* __restrict__ pos,
    const float* __restrict__ Wg, const float* __restrict__ bg)
{
    __shared__ float bsum[HH];
    const int t = threadIdx.x;
    if (t < HH) bsum[t] = 0.f;
    __syncthreads();

    const int lane = t & 31;
    const int h = lane >> 3, sub = lane & 7;
    const int wpb = blockDim.x >> 5;
    const int warp = t >> 5;

    const float wg0 = Wg[h], wg1 = Wg[4 + h], wg2 = Wg[8 + h], wg3 = Wg[12 + h];
    const float bgh = bg[h];

    float psum = 0.f;
    const size_t off = (size_t)(h * DD + sub * 8);

    const int stride = gridDim.x * wpb * 4;
    for (int e = (blockIdx.x * wpb + warp) * 4; e < EE; e += stride) {
        int srcs[4], dsts[4];
        #pragma unroll
        for (int j = 0; j < 4; j++) {
            srcs[j] = __ldg(&ei[e + j]);
            dsts[j] = __ldg(&ei[EE + e + j]);
        }
        uint4 qa[4], ka[4];
        #pragma unroll
        for (int j = 0; j < 4; j++) {
            qa[j] = *(const uint4*)(g_qh + (size_t)srcs[j] * HD + off);
            ka[j] = *(const uint4*)(g_kh + (size_t)dsts[j] * HD + off);
        }
        float d[4];
        #pragma unroll
        for (int j = 0; j < 4; j++) {
            const __half2* hq = (const __half2*)&qa[j];
            const __half2* hk = (const __half2*)&ka[j];
            float s = 0.f;
            #pragma unroll
            for (int i = 0; i < 4; i++) {
                float2 fq = __half22float2(hq[i]);
                float2 fk = __half22float2(hk[i]);
                s += fq.x * fk.x + fq.y * fk.y;
            }
            d[j] = s;
        }
        #pragma unroll
        for (int m = 4; m >= 1; m >>= 1) {
            #pragma unroll
            for (int j = 0; j < 4; j++)
                d[j] += __shfl_xor_sync(0xffffffffu, d[j], m);
        }

        if (sub == 0) {
            #pragma unroll
            for (int j = 0; j < 4; j++) {
                const int s0 = srcs[j], d0 = dsts[j];
                float dx = __ldg(&pos[d0 * 3 + 0]) - __ldg(&pos[s0 * 3 + 0]);
                float dy = __ldg(&pos[d0 * 3 + 1]) - __ldg(&pos[s0 * 3 + 1]);
                float dz = __ldg(&pos[d0 * 3 + 2]) - __ldg(&pos[s0 * 3 + 2]);
                float dist = sqrtf(dx * dx + dy * dy + dz * dz);
                float inv = 1.f / (dist + 1e-8f);
                float gw = bgh + dist * wg0 + dx * inv * wg1 + dy * inv * wg2 + dz * inv * wg3;
                float p = expf(d[j] * 0.125f + gw);
                atomicAdd(&g_acc[d0 * HH + h], p);
                psum += p;
            }
        }
    }

    if (sub == 0) atomicAdd(&bsum[h], psum);
    __syncthreads();
    if (t < HH) atomicAdd(&g_hsum[t], bsum[t]);
}

// ---------------- K3: out[n,d] = bo[d] + sum_h coef[n,h] * u[n,h*64+d] ----------------
__global__ __launch_bounds__(256) void out_k(
    const float* __restrict__ bo, float* __restrict__ out)
{
    __shared__ float sInv[HH];
    const int t = threadIdx.x;
    if (t < HH) sInv[t] = 1.f / g_hsum[t];
    __syncthreads();

    const int node = blockIdx.x * 4 + (t >> 6);
    const int d = t & 63;
    const float* u = g_u + (size_t)node * HD;
    float acc = bo[d];
    #pragma unroll
    for (int h = 0; h < HH; h++)
        acc += g_acc[node * HH + h] * sInv[h] * u[h * 64 + d];
    out[(size_t)node * DD + d] = acc;
}

// ---------------------------------------------------------------
extern "C" void kernel_launch(void* const* d_in, const int* in_sizes, int n_in,
                              void* d_out, int out_size)
{
    const float* x   = (const float*)d_in[0];
    const int*   ei  = (const int*)d_in[1];
    const float* pos = (const float*)d_in[2];
    const float* Wq  = (const float*)d_in[3];
    const float* bq  = (const float*)d_in[4];
    const float* Wk  = (const float*)d_in[5];
    const float* bk  = (const float*)d_in[6];
    const float* Wv  = (const float*)d_in[7];
    const float* bv  = (const float*)d_in[8];
    const float* Wg  = (const float*)d_in[9];
    const float* bg  = (const float*)d_in[10];
    const float* Wo  = (const float*)d_in[11];
    const float* bo  = (const float*)d_in[12];
    float*       out = (float*)d_out;

    cudaFuncSetAttribute(gemm_mma, cudaFuncAttributeMaxDynamicSharedMemorySize, SMEM_TOTAL);

    conv_x_k<<<(NN * CIN / 4) / 256, 256>>>(x);
    conv_w_k<<<256, 768>>>(Wq, Wk, Wv, Wo, bv);
    init_k<<<(NN * HH + 255) / 256, 256>>>();

    dim3 ggrid(6, (NN + 127) / 128);
    gemm_mma<<<ggrid, 256, SMEM_TOTAL>>>(bq, bk);

    edge_k<<<1184, 256>>>(ei, pos, Wg, bg);

    out_k<<<NN / 4, 256>>>(bo, out);
}

// round 15
// speedup vs baseline: 1.2135x; 1.2135x over previous
#include <cuda_runtime.h>
#include <cuda_fp16.h>
#include <cstdint>

#define NN 50000
#define EE 800000
#define CIN 256
#define HD  256   // H*D
#define DD  64
#define HH  4

// ---------------- device scratch ----------------
__device__ __half g_xh[(size_t)NN * CIN];    // x in fp16
__device__ __half g_wh[768 * 256];           // [outcol][k]  (B^T layout), fp16
__device__ float g_bvo[256];
__device__ __half g_qh[(size_t)NN * HD];     // q in fp16
__device__ __half g_kh[(size_t)NN * HD];     // k in fp16
__device__ float g_u[(size_t)NN * HD];       // u = x @ (Wv@Wo per head) + bvo
__device__ float g_acc[NN * HH];
__device__ float g_hsum[HH];

__device__ __forceinline__ uint32_t smem_u32(const void* p) {
    uint32_t a;
    asm("{ .reg .u64 t; cvta.to.shared.u64 t, %1; cvt.u32.u64 %0, t; }" : "=r"(a) : "l"(p));
    return a;
}
__device__ __forceinline__ void ldmatrix_x4(uint32_t& r0, uint32_t& r1, uint32_t& r2, uint32_t& r3, uint32_t addr) {
    asm volatile("ldmatrix.sync.aligned.m8n8.x4.shared.b16 {%0,%1,%2,%3}, [%4];"
        : "=r"(r0), "=r"(r1), "=r"(r2), "=r"(r3) : "r"(addr));
}
__device__ __forceinline__ void cp_async16(uint32_t smem_addr, const void* gptr) {
    asm volatile("cp.async.cg.shared.global [%0], [%1], 16;" :: "r"(smem_addr), "l"(gptr));
}
#define CP_COMMIT() asm volatile("cp.async.commit_group;" ::: "memory")
#define CP_WAIT(n)  asm volatile("cp.async.wait_group %0;" :: "n"(n) : "memory")

// ---------------- K0a: x -> fp16 ----------------
__global__ __launch_bounds__(256) void conv_x_k(const float* __restrict__ x) {
    size_t g = (size_t)blockIdx.x * 256 + threadIdx.x;   // float4 index
    float4 v = ((const float4*)x)[g];
    __half2* ph = (__half2*)g_xh;
    ph[g * 2]     = __floats2half2_rn(v.x, v.y);
    ph[g * 2 + 1] = __floats2half2_rn(v.z, v.w);
}

// ---------------- K0b: combined weight [Wq|Wk|Wvo], transposed, fp16 ----------------
__global__ __launch_bounds__(768) void conv_w_k(
    const float* __restrict__ Wq, const float* __restrict__ Wk,
    const float* __restrict__ Wv, const float* __restrict__ Wo,
    const float* __restrict__ bv)
{
    __shared__ float sWv[256];
    const int c = blockIdx.x;          // k index 0..255
    const int t = threadIdx.x;         // output col 0..767
    if (t < 256) sWv[t] = Wv[c * 256 + t];
    __syncthreads();
    float w;
    if (t < 256)       w = Wq[c * 256 + t];
    else if (t < 512)  w = Wk[c * 256 + (t - 256)];
    else {
        int i = t - 512, h = i >> 6, d = i & 63;
        float s = 0.f;
        #pragma unroll 8
        for (int j = 0; j < 64; j++) s += sWv[h * 64 + j] * Wo[(h * 64 + j) * 64 + d];
        w = s;
    }
    g_wh[t * 256 + c] = __float2half_rn(w);
    if (c == 0 && t >= 512) {
        int i = t - 512, h = i >> 6, d = i & 63;
        float s = 0.f;
        for (int j = 0; j < 64; j++) s += bv[h * 64 + j] * Wo[(h * 64 + j) * 64 + d];
        g_bvo[i] = s;
    }
}

// ---------------- K0c: zero accumulators ----------------
__global__ void init_k() {
    int i = blockIdx.x * blockDim.x + threadIdx.x;
    if (i < NN * HH) g_acc[i] = 0.f;
    if (i < HH)      g_hsum[i] = 0.f;
}

// ---------------- K1: single-pass fp16 HMMA GEMM [50048 x 256] @ [256 x 768] ----------------
// Block 128x128, 8 warps (warp tile 32x64), k-chunk 64 (4 chunks), 2-stage cp.async pipeline.
// XOR-swizzled smem: phys(row, unit16) = row*128B + (unit ^ (row&7))*16B.  (R11 config)
#define STAGE_BYTES 16384
#define SMEM_TOTAL  (4 * STAGE_BYTES)        // A0,A1,B0,B1 = 65536 bytes -> 2 blocks/SM

__device__ __forceinline__ void mma_fp16(float* c, const uint32_t* a, const uint32_t* b) {
    asm volatile("mma.sync.aligned.m16n8k16.row.col.f32.f16.f16.f32 "
        "{%0,%1,%2,%3}, {%4,%5,%6,%7}, {%8,%9}, {%0,%1,%2,%3};"
        : "+f"(c[0]), "+f"(c[1]), "+f"(c[2]), "+f"(c[3])
        : "r"(a[0]), "r"(a[1]), "r"(a[2]), "r"(a[3]), "r"(b[0]), "r"(b[1]));
}

__global__ __launch_bounds__(256, 2) void gemm_mma(
    const float* __restrict__ bq, const float* __restrict__ bk)
{
    extern __shared__ __align__(16) char smem[];
    const uint32_t base = smem_u32(smem);
    const uint32_t aBase = base;                       // stages 0/1 at +0 / +STAGE_BYTES
    const uint32_t bBase = base + 2 * STAGE_BYTES;     // stages 0/1

    const int t = threadIdx.x, wid = t >> 5, lane = t & 31;
    const int gr = lane >> 2, q4 = lane & 3;
    const int rowBase = blockIdx.y * 128;
    const int col0 = blockIdx.x * 128;
    const int m0 = (wid >> 1) * 32, n0 = (wid & 1) * 64;

    // ---- cp.async indexing: thread t copies 4 x 16B for A and for B per chunk
    const int lrow = t >> 1;             // 0..127
    const int lq   = (t & 1) * 4;        // first unit (0 or 4)
    const int xr   = lrow & 7;           // store swizzle
    const int growA = (rowBase + lrow < NN) ? rowBase + lrow : NN - 1;  // clamp; rows>=NN never stored
    const __half* gA = g_xh + (size_t)growA * 256;
    const __half* gB = g_wh + (size_t)(col0 + lrow) * 256;
    const uint32_t sAr = aBase + (uint32_t)lrow * 128;
    const uint32_t sBr = bBase + (uint32_t)lrow * 128;
    uint32_t stU[4];
    #pragma unroll
    for (int i = 0; i < 4; i++) stU[i] = (uint32_t)(((lq + i) ^ xr) << 4);

    // ---- ldmatrix row-base addresses (swizzle unit added per k-step)
    const int arow = (lane & 15);
    const int brow = (lane & 7) + ((lane >> 4) & 1) * 8;
    const uint32_t lx7 = (uint32_t)(lane & 7);
    const uint32_t uAbit = (uint32_t)(lane >> 4);          // A: unit lsb
    const uint32_t uBbit = (uint32_t)((lane >> 3) & 1);    // B: unit lsb
    uint32_t addrA[2], addrB[4];
    #pragma unroll
    for (int f = 0; f < 2; f++)
        addrA[f] = aBase + (uint32_t)(m0 + f * 16 + arow) * 128;
    #pragma unroll
    for (int gp = 0; gp < 4; gp++)
        addrB[gp] = bBase + (uint32_t)(n0 + gp * 16 + brow) * 128;

    float C[2][8][4] = {};

    // prologue: chunk 0 -> stage 0
    #pragma unroll
    for (int i = 0; i < 4; i++) {
        cp_async16(sAr + stU[i], gA + (lq + i) * 8);
        cp_async16(sBr + stU[i], gB + (lq + i) * 8);
    }
    CP_COMMIT();

    #pragma unroll
    for (int kc = 0; kc < 4; kc++) {
        const uint32_t buf = (kc & 1) ? STAGE_BYTES : 0u;
        if (kc < 3) {
            const uint32_t nbuf = ((kc + 1) & 1) ? STAGE_BYTES : 0u;
            const int kt = (kc + 1) * 64;
            #pragma unroll
            for (int i = 0; i < 4; i++) {
                cp_async16(sAr + nbuf + stU[i], gA + kt + (lq + i) * 8);
                cp_async16(sBr + nbuf + stU[i], gB + kt + (lq + i) * 8);
            }
            CP_COMMIT();
            CP_WAIT(1);
        } else {
            CP_WAIT(0);
        }
        __syncthreads();

        #pragma unroll
        for (int s = 0; s < 4; s++) {
            const uint32_t uA = ((((uint32_t)s << 1) | uAbit) ^ lx7) << 4;
            const uint32_t uB = ((((uint32_t)s << 1) | uBbit) ^ lx7) << 4;
            uint32_t a[2][4], b[8][2];
            #pragma unroll
            for (int f = 0; f < 2; f++)
                ldmatrix_x4(a[f][0], a[f][1], a[f][2], a[f][3], addrA[f] + buf + uA);
            #pragma unroll
            for (int gp = 0; gp < 4; gp++)
                ldmatrix_x4(b[2 * gp][0], b[2 * gp][1], b[2 * gp + 1][0], b[2 * gp + 1][1],
                            addrB[gp] + buf + uB);
            #pragma unroll
            for (int f = 0; f < 2; f++)
                #pragma unroll
                for (int g = 0; g < 8; g++)
                    mma_fp16(C[f][g], a[f], b[g]);
        }
        __syncthreads();
    }

    // epilogue: bias; q,k -> fp16, u -> fp32
    const int which = col0 >> 8;
    const int wcol0 = col0 & 255;

    #pragma unroll
    for (int f = 0; f < 2; f++) {
        int r0 = rowBase + m0 + f * 16 + gr;
        #pragma unroll
        for (int g = 0; g < 8; g++) {
            int c = wcol0 + n0 + g * 8 + q4 * 2;
            if (which < 2) {
                const float* bias = (which == 0) ? bq : bk;
                __half* OUT = (which == 0) ? g_qh : g_kh;
                float b0 = bias[c], b1 = bias[c + 1];
                if (r0 < NN)
                    *(__half2*)&OUT[(size_t)r0 * 256 + c] =
                        __floats2half2_rn(C[f][g][0] + b0, C[f][g][1] + b1);
                if (r0 + 8 < NN)
                    *(__half2*)&OUT[(size_t)(r0 + 8) * 256 + c] =
                        __floats2half2_rn(C[f][g][2] + b0, C[f][g][3] + b1);
            } else {
                float b0 = g_bvo[c], b1 = g_bvo[c + 1];
                if (r0 < NN)
                    *(float2*)&g_u[(size_t)r0 * 256 + c] =
                        make_float2(C[f][g][0] + b0, C[f][g][1] + b1);
                if (r0 + 8 < NN)
                    *(float2*)&g_u[(size_t)(r0 + 8) * 256 + c] =
                        make_float2(C[f][g][2] + b0, C[f][g][3] + b1);
            }
        }
    }
}

// ---------------- K2: per-edge scores -> exp -> scalar scatter-add ----------------
// 2 edges per warp iteration; xor-shuffle leaves the reduced dot in ALL 8 lanes of
// each head group, so edge j's geometry/exp/atomic runs on lane sub==j (parallel tails).
__global__ __launch_bounds__(256) void edge_k(
    const int* __restrict__ ei,
    const float* __restrict__ pos,
    const float* __restrict__ Wg, const float* __restrict__ bg)
{
    __shared__ float bsum[HH];
    const int t = threadIdx.x;
    if (t < HH) bsum[t] = 0.f;
    __syncthreads();

    const int lane = t & 31;
    const int h = lane >> 3, sub = lane & 7;
    const int wpb = blockDim.x >> 5;
    const int warp = t >> 5;

    const float wg0 = Wg[h], wg1 = Wg[4 + h], wg2 = Wg[8 + h], wg3 = Wg[12 + h];
    const float bgh = bg[h];

    float psum = 0.f;
    const size_t off = (size_t)(h * DD + sub * 8);

    const int stride = gridDim.x * wpb * 2;
    for (int e = (blockIdx.x * wpb + warp) * 2; e < EE; e += stride) {
        // EE even, e even -> e+1 always valid
        const int src0 = __ldg(&ei[e]);
        const int dst0 = __ldg(&ei[EE + e]);
        const int src1 = __ldg(&ei[e + 1]);
        const int dst1 = __ldg(&ei[EE + e + 1]);

        uint4 qa0 = *(const uint4*)(g_qh + (size_t)src0 * HD + off);
        uint4 ka0 = *(const uint4*)(g_kh + (size_t)dst0 * HD + off);
        uint4 qa1 = *(const uint4*)(g_qh + (size_t)src1 * HD + off);
        uint4 ka1 = *(const uint4*)(g_kh + (size_t)dst1 * HD + off);

        float d0 = 0.f, d1 = 0.f;
        {
            const __half2* hq = (const __half2*)&qa0;
            const __half2* hk = (const __half2*)&ka0;
            #pragma unroll
            for (int i = 0; i < 4; i++) {
                float2 fq = __half22float2(hq[i]);
                float2 fk = __half22float2(hk[i]);
                d0 += fq.x * fk.x + fq.y * fk.y;
            }
        }
        {
            const __half2* hq = (const __half2*)&qa1;
            const __half2* hk = (const __half2*)&ka1;
            #pragma unroll
            for (int i = 0; i < 4; i++) {
                float2 fq = __half22float2(hq[i]);
                float2 fk = __half22float2(hk[i]);
                d1 += fq.x * fk.x + fq.y * fk.y;
            }
        }
        #pragma unroll
        for (int m = 4; m >= 1; m >>= 1) {
            d0 += __shfl_xor_sync(0xffffffffu, d0, m);
            d1 += __shfl_xor_sync(0xffffffffu, d1, m);
        }

        // parallel geometry tails: lane sub==0 -> edge0, lane sub==1 -> edge1
        if (sub < 2) {
            const int s0 = (sub == 0) ? src0 : src1;
            const int dd = (sub == 0) ? dst0 : dst1;
            const float dj = (sub == 0) ? d0 : d1;
            float dx = __ldg(&pos[dd * 3 + 0]) - __ldg(&pos[s0 * 3 + 0]);
            float dy = __ldg(&pos[dd * 3 + 1]) - __ldg(&pos[s0 * 3 + 1]);
            float dz = __ldg(&pos[dd * 3 + 2]) - __ldg(&pos[s0 * 3 + 2]);
            float dist = sqrtf(dx * dx + dy * dy + dz * dz);
            float inv = 1.f / (dist + 1e-8f);
            float gw = bgh + dist * wg0 + dx * inv * wg1 + dy * inv * wg2 + dz * inv * wg3;
            float p = expf(dj * 0.125f + gw);
            atomicAdd(&g_acc[dd * HH + h], p);
            psum += p;
        }
    }

    if (sub < 2) atomicAdd(&bsum[h], psum);
    __syncthreads();
    if (t < HH) atomicAdd(&g_hsum[t], bsum[t]);
}

// ---------------- K3: out[n,d] = bo[d] + sum_h coef[n,h] * u[n,h*64+d] ----------------
__global__ __launch_bounds__(256) void out_k(
    const float* __restrict__ bo, float* __restrict__ out)
{
    __shared__ float sInv[HH];
    const int t = threadIdx.x;
    if (t < HH) sInv[t] = 1.f / g_hsum[t];
    __syncthreads();

    const int node = blockIdx.x * 4 + (t >> 6);
    const int d = t & 63;
    const float* u = g_u + (size_t)node * HD;
    float acc = bo[d];
    #pragma unroll
    for (int h = 0; h < HH; h++)
        acc += g_acc[node * HH + h] * sInv[h] * u[h * 64 + d];
    out[(size_t)node * DD + d] = acc;
}

// ---------------------------------------------------------------
extern "C" void kernel_launch(void* const* d_in, const int* in_sizes, int n_in,
                              void* d_out, int out_size)
{
    const float* x   = (const float*)d_in[0];
    const int*   ei  = (const int*)d_in[1];
    const float* pos = (const float*)d_in[2];
    const float* Wq  = (const float*)d_in[3];
    const float* bq  = (const float*)d_in[4];
    const float* Wk  = (const float*)d_in[5];
    const float* bk  = (const float*)d_in[6];
    const float* Wv  = (const float*)d_in[7];
    const float* bv  = (const float*)d_in[8];
    const float* Wg  = (const float*)d_in[9];
    const float* bg  = (const float*)d_in[10];
    const float* Wo  = (const float*)d_in[11];
    const float* bo  = (const float*)d_in[12];
    float*       out = (float*)d_out;

    cudaFuncSetAttribute(gemm_mma, cudaFuncAttributeMaxDynamicSharedMemorySize, SMEM_TOTAL);

    conv_x_k<<<(NN * CIN / 4) / 256, 256>>>(x);
    conv_w_k<<<256, 768>>>(Wq, Wk, Wv, Wo, bv);
    init_k<<<(NN * HH + 255) / 256, 256>>>();

    dim3 ggrid(6, (NN + 127) / 128);
    gemm_mma<<<ggrid, 256, SMEM_TOTAL>>>(bq, bk);

    edge_k<<<2048, 256>>>(ei, pos, Wg, bg);

    out_k<<<NN / 4, 256>>>(bo, out);
}

// round 16
// speedup vs baseline: 1.2144x; 1.0007x over previous
#include <cuda_runtime.h>
#include <cuda_fp16.h>
#include <cstdint>

#define NN 50000
#define EE 800000
#define CIN 256
#define HD  256   // H*D
#define DD  64
#define HH  4

// ---------------- device scratch ----------------
__device__ __half g_xh[(size_t)NN * CIN];    // x in fp16
__device__ __half g_wh[768 * 256];           // [outcol][k]  (B^T layout), fp16
__device__ float g_bvo[256];
__device__ __half g_qh[(size_t)NN * HD];     // q in fp16
__device__ __half g_kh[(size_t)NN * HD];     // k in fp16
__device__ float g_u[(size_t)NN * HD];       // u = x @ (Wv@Wo per head) + bvo
__device__ float g_acc[NN * HH];
__device__ float g_hsum[HH];

__device__ __forceinline__ uint32_t smem_u32(const void* p) {
    uint32_t a;
    asm("{ .reg .u64 t; cvta.to.shared.u64 t, %1; cvt.u32.u64 %0, t; }" : "=r"(a) : "l"(p));
    return a;
}
__device__ __forceinline__ void ldmatrix_x4(uint32_t& r0, uint32_t& r1, uint32_t& r2, uint32_t& r3, uint32_t addr) {
    asm volatile("ldmatrix.sync.aligned.m8n8.x4.shared.b16 {%0,%1,%2,%3}, [%4];"
        : "=r"(r0), "=r"(r1), "=r"(r2), "=r"(r3) : "r"(addr));
}
__device__ __forceinline__ void cp_async16(uint32_t smem_addr, const void* gptr) {
    asm volatile("cp.async.cg.shared.global [%0], [%1], 16;" :: "r"(smem_addr), "l"(gptr));
}
#define CP_COMMIT() asm volatile("cp.async.commit_group;" ::: "memory")
#define CP_WAIT(n)  asm volatile("cp.async.wait_group %0;" :: "n"(n) : "memory")

// ---------------- K0a: x -> fp16 ----------------
__global__ __launch_bounds__(256) void conv_x_k(const float* __restrict__ x) {
    size_t g = (size_t)blockIdx.x * 256 + threadIdx.x;   // float4 index
    float4 v = ((const float4*)x)[g];
    __half2* ph = (__half2*)g_xh;
    ph[g * 2]     = __floats2half2_rn(v.x, v.y);
    ph[g * 2 + 1] = __floats2half2_rn(v.z, v.w);
}

// ---------------- K0b: combined weight [Wq|Wk|Wvo], transposed, fp16 ----------------
__global__ __launch_bounds__(768) void conv_w_k(
    const float* __restrict__ Wq, const float* __restrict__ Wk,
    const float* __restrict__ Wv, const float* __restrict__ Wo,
    const float* __restrict__ bv)
{
    __shared__ float sWv[256];
    const int c = blockIdx.x;          // k index 0..255
    const int t = threadIdx.x;         // output col 0..767
    if (t < 256) sWv[t] = Wv[c * 256 + t];
    __syncthreads();
    float w;
    if (t < 256)       w = Wq[c * 256 + t];
    else if (t < 512)  w = Wk[c * 256 + (t - 256)];
    else {
        int i = t - 512, h = i >> 6, d = i & 63;
        float s = 0.f;
        #pragma unroll 8
        for (int j = 0; j < 64; j++) s += sWv[h * 64 + j] * Wo[(h * 64 + j) * 64 + d];
        w = s;
    }
    g_wh[t * 256 + c] = __float2half_rn(w);
    if (c == 0 && t >= 512) {
        int i = t - 512, h = i >> 6, d = i & 63;
        float s = 0.f;
        for (int j = 0; j < 64; j++) s += bv[h * 64 + j] * Wo[(h * 64 + j) * 64 + d];
        g_bvo[i] = s;
    }
}

// ---------------- K0c: zero accumulators ----------------
__global__ void init_k() {
    int i = blockIdx.x * blockDim.x + threadIdx.x;
    if (i < NN * HH) g_acc[i] = 0.f;
    if (i < HH)      g_hsum[i] = 0.f;
}

// ---------------- K1: single-pass fp16 HMMA GEMM [50048 x 256] @ [256 x 768] ----------------
// Block 128x128, 8 warps (warp tile 32x64), k-chunk 64 (4 chunks), 2-stage cp.async pipeline.
// XOR-swizzled smem: phys(row, unit16) = row*128B + (unit ^ (row&7))*16B.  (R11 config)
#define STAGE_BYTES 16384
#define SMEM_TOTAL  (4 * STAGE_BYTES)        // A0,A1,B0,B1 = 65536 bytes -> 2 blocks/SM

__device__ __forceinline__ void mma_fp16(float* c, const uint32_t* a, const uint32_t* b) {
    asm volatile("mma.sync.aligned.m16n8k16.row.col.f32.f16.f16.f32 "
        "{%0,%1,%2,%3}, {%4,%5,%6,%7}, {%8,%9}, {%0,%1,%2,%3};"
        : "+f"(c[0]), "+f"(c[1]), "+f"(c[2]), "+f"(c[3])
        : "r"(a[0]), "r"(a[1]), "r"(a[2]), "r"(a[3]), "r"(b[0]), "r"(b[1]));
}

__global__ __launch_bounds__(256, 2) void gemm_mma(
    const float* __restrict__ bq, const float* __restrict__ bk)
{
    extern __shared__ __align__(16) char smem[];
    const uint32_t base = smem_u32(smem);
    const uint32_t aBase = base;                       // stages 0/1 at +0 / +STAGE_BYTES
    const uint32_t bBase = base + 2 * STAGE_BYTES;     // stages 0/1

    const int t = threadIdx.x, wid = t >> 5, lane = t & 31;
    const int gr = lane >> 2, q4 = lane & 3;
    const int rowBase = blockIdx.y * 128;
    const int col0 = blockIdx.x * 128;
    const int m0 = (wid >> 1) * 32, n0 = (wid & 1) * 64;

    // ---- cp.async indexing: thread t copies 4 x 16B for A and for B per chunk
    const int lrow = t >> 1;             // 0..127
    const int lq   = (t & 1) * 4;        // first unit (0 or 4)
    const int xr   = lrow & 7;           // store swizzle
    const int growA = (rowBase + lrow < NN) ? rowBase + lrow : NN - 1;  // clamp; rows>=NN never stored
    const __half* gA = g_xh + (size_t)growA * 256;
    const __half* gB = g_wh + (size_t)(col0 + lrow) * 256;
    const uint32_t sAr = aBase + (uint32_t)lrow * 128;
    const uint32_t sBr = bBase + (uint32_t)lrow * 128;
    uint32_t stU[4];
    #pragma unroll
    for (int i = 0; i < 4; i++) stU[i] = (uint32_t)(((lq + i) ^ xr) << 4);

    // ---- ldmatrix row-base addresses (swizzle unit added per k-step)
    const int arow = (lane & 15);
    const int brow = (lane & 7) + ((lane >> 4) & 1) * 8;
    const uint32_t lx7 = (uint32_t)(lane & 7);
    const uint32_t uAbit = (uint32_t)(lane >> 4);          // A: unit lsb
    const uint32_t uBbit = (uint32_t)((lane >> 3) & 1);    // B: unit lsb
    uint32_t addrA[2], addrB[4];
    #pragma unroll
    for (int f = 0; f < 2; f++)
        addrA[f] = aBase + (uint32_t)(m0 + f * 16 + arow) * 128;
    #pragma unroll
    for (int gp = 0; gp < 4; gp++)
        addrB[gp] = bBase + (uint32_t)(n0 + gp * 16 + brow) * 128;

    float C[2][8][4] = {};

    // prologue: chunk 0 -> stage 0
    #pragma unroll
    for (int i = 0; i < 4; i++) {
        cp_async16(sAr + stU[i], gA + (lq + i) * 8);
        cp_async16(sBr + stU[i], gB + (lq + i) * 8);
    }
    CP_COMMIT();

    #pragma unroll
    for (int kc = 0; kc < 4; kc++) {
        const uint32_t buf = (kc & 1) ? STAGE_BYTES : 0u;
        if (kc < 3) {
            const uint32_t nbuf = ((kc + 1) & 1) ? STAGE_BYTES : 0u;
            const int kt = (kc + 1) * 64;
            #pragma unroll
            for (int i = 0; i < 4; i++) {
                cp_async16(sAr + nbuf + stU[i], gA + kt + (lq + i) * 8);
                cp_async16(sBr + nbuf + stU[i], gB + kt + (lq + i) * 8);
            }
            CP_COMMIT();
            CP_WAIT(1);
        } else {
            CP_WAIT(0);
        }
        __syncthreads();

        #pragma unroll
        for (int s = 0; s < 4; s++) {
            const uint32_t uA = ((((uint32_t)s << 1) | uAbit) ^ lx7) << 4;
            const uint32_t uB = ((((uint32_t)s << 1) | uBbit) ^ lx7) << 4;
            uint32_t a[2][4], b[8][2];
            #pragma unroll
            for (int f = 0; f < 2; f++)
                ldmatrix_x4(a[f][0], a[f][1], a[f][2], a[f][3], addrA[f] + buf + uA);
            #pragma unroll
            for (int gp = 0; gp < 4; gp++)
                ldmatrix_x4(b[2 * gp][0], b[2 * gp][1], b[2 * gp + 1][0], b[2 * gp + 1][1],
                            addrB[gp] + buf + uB);
            #pragma unroll
            for (int f = 0; f < 2; f++)
                #pragma unroll
                for (int g = 0; g < 8; g++)
                    mma_fp16(C[f][g], a[f], b[g]);
        }
        __syncthreads();
    }

    // epilogue: bias; q,k -> fp16, u -> fp32
    const int which = col0 >> 8;
    const int wcol0 = col0 & 255;

    #pragma unroll
    for (int f = 0; f < 2; f++) {
        int r0 = rowBase + m0 + f * 16 + gr;
        #pragma unroll
        for (int g = 0; g < 8; g++) {
            int c = wcol0 + n0 + g * 8 + q4 * 2;
            if (which < 2) {
                const float* bias = (which == 0) ? bq : bk;
                __half* OUT = (which == 0) ? g_qh : g_kh;
                float b0 = bias[c], b1 = bias[c + 1];
                if (r0 < NN)
                    *(__half2*)&OUT[(size_t)r0 * 256 + c] =
                        __floats2half2_rn(C[f][g][0] + b0, C[f][g][1] + b1);
                if (r0 + 8 < NN)
                    *(__half2*)&OUT[(size_t)(r0 + 8) * 256 + c] =
                        __floats2half2_rn(C[f][g][2] + b0, C[f][g][3] + b1);
            } else {
                float b0 = g_bvo[c], b1 = g_bvo[c + 1];
                if (r0 < NN)
                    *(float2*)&g_u[(size_t)r0 * 256 + c] =
                        make_float2(C[f][g][0] + b0, C[f][g][1] + b1);
                if (r0 + 8 < NN)
                    *(float2*)&g_u[(size_t)(r0 + 8) * 256 + c] =
                        make_float2(C[f][g][2] + b0, C[f][g][3] + b1);
            }
        }
    }
}

// ---------------- K2: per-edge scores -> exp -> scalar scatter-add ----------------
// 2 edges per warp iteration; xor-shuffle leaves the reduced dot in ALL 8 lanes of
// each head group, so edge j's geometry/exp/atomic runs on lane sub==j (parallel tails).
__global__ __launch_bounds__(256) void edge_k(
    const int* __restrict__ ei,
    const float* __restrict__ pos,
    const float* __restrict__ Wg, const float* __restrict__ bg)
{
    __shared__ float bsum[HH];
    const int t = threadIdx.x;
    if (t < HH) bsum[t] = 0.f;
    __syncthreads();

    const int lane = t & 31;
    const int h = lane >> 3, sub = lane & 7;
    const int wpb = blockDim.x >> 5;
    const int warp = t >> 5;

    const float wg0 = Wg[h], wg1 = Wg[4 + h], wg2 = Wg[8 + h], wg3 = Wg[12 + h];
    const float bgh = bg[h];

    float psum = 0.f;
    const size_t off = (size_t)(h * DD + sub * 8);

    const int stride = gridDim.x * wpb * 2;
    for (int e = (blockIdx.x * wpb + warp) * 2; e < EE; e += stride) {
        // EE even, e even -> e+1 always valid
        const int src0 = __ldg(&ei[e]);
        const int dst0 = __ldg(&ei[EE + e]);
        const int src1 = __ldg(&ei[e + 1]);
        const int dst1 = __ldg(&ei[EE + e + 1]);

        uint4 qa0 = *(const uint4*)(g_qh + (size_t)src0 * HD + off);
        uint4 ka0 = *(const uint4*)(g_kh + (size_t)dst0 * HD + off);
        uint4 qa1 = *(const uint4*)(g_qh + (size_t)src1 * HD + off);
        uint4 ka1 = *(const uint4*)(g_kh + (size_t)dst1 * HD + off);

        float d0 = 0.f, d1 = 0.f;
        {
            const __half2* hq = (const __half2*)&qa0;
            const __half2* hk = (const __half2*)&ka0;
            #pragma unroll
            for (int i = 0; i < 4; i++) {
                float2 fq = __half22float2(hq[i]);
                float2 fk = __half22float2(hk[i]);
                d0 += fq.x * fk.x + fq.y * fk.y;
            }
        }
        {
            const __half2* hq = (const __half2*)&qa1;
            const __half2* hk = (const __half2*)&ka1;
            #pragma unroll
            for (int i = 0; i < 4; i++) {
                float2 fq = __half22float2(hq[i]);
                float2 fk = __half22float2(hk[i]);
                d1 += fq.x * fk.x + fq.y * fk.y;
            }
        }
        #pragma unroll
        for (int m = 4; m >= 1; m >>= 1) {
            d0 += __shfl_xor_sync(0xffffffffu, d0, m);
            d1 += __shfl_xor_sync(0xffffffffu, d1, m);
        }

        // parallel geometry tails: lane sub==0 -> edge0, lane sub==1 -> edge1
        if (sub < 2) {
            const int s0 = (sub == 0) ? src0 : src1;
            const int dd = (sub == 0) ? dst0 : dst1;
            const float dj = (sub == 0) ? d0 : d1;
            float dx = __ldg(&pos[dd * 3 + 0]) - __ldg(&pos[s0 * 3 + 0]);
            float dy = __ldg(&pos[dd * 3 + 1]) - __ldg(&pos[s0 * 3 + 1]);
            float dz = __ldg(&pos[dd * 3 + 2]) - __ldg(&pos[s0 * 3 + 2]);
            float dist = sqrtf(dx * dx + dy * dy + dz * dz);
            float inv = 1.f / (dist + 1e-8f);
            float gw = bgh + dist * wg0 + dx * inv * wg1 + dy * inv * wg2 + dz * inv * wg3;
            float p = expf(dj * 0.125f + gw);
            atomicAdd(&g_acc[dd * HH + h], p);
            psum += p;
        }
    }

    if (sub < 2) atomicAdd(&bsum[h], psum);
    __syncthreads();
    if (t < HH) atomicAdd(&g_hsum[t], bsum[t]);
}

// ---------------- K3: out[n,d] = bo[d] + sum_h coef[n,h] * u[n,h*64+d] ----------------
__global__ __launch_bounds__(256) void out_k(
    const float* __restrict__ bo, float* __restrict__ out)
{
    __shared__ float sInv[HH];
    const int t = threadIdx.x;
    if (t < HH) sInv[t] = 1.f / g_hsum[t];
    __syncthreads();

    const int node = blockIdx.x * 4 + (t >> 6);
    const int d = t & 63;
    const float* u = g_u + (size_t)node * HD;
    float acc = bo[d];
    #pragma unroll
    for (int h = 0; h < HH; h++)
        acc += g_acc[node * HH + h] * sInv[h] * u[h * 64 + d];
    out[(size_t)node * DD + d] = acc;
}

// ---------------------------------------------------------------
extern "C" void kernel_launch(void* const* d_in, const int* in_sizes, int n_in,
                              void* d_out, int out_size)
{
    const float* x   = (const float*)d_in[0];
    const int*   ei  = (const int*)d_in[1];
    const float* pos = (const float*)d_in[2];
    const float* Wq  = (const float*)d_in[3];
    const float* bq  = (const float*)d_in[4];
    const float* Wk  = (const float*)d_in[5];
    const float* bk  = (const float*)d_in[6];
    const float* Wv  = (const float*)d_in[7];
    const float* bv  = (const float*)d_in[8];
    const float* Wg  = (const float*)d_in[9];
    const float* bg  = (const float*)d_in[10];
    const float* Wo  = (const float*)d_in[11];
    const float* bo  = (const float*)d_in[12];
    float*       out = (float*)d_out;

    cudaFuncSetAttribute(gemm_mma, cudaFuncAttributeMaxDynamicSharedMemorySize, SMEM_TOTAL);

    conv_x_k<<<(NN * CIN / 4) / 256, 256>>>(x);
    conv_w_k<<<256, 768>>>(Wq, Wk, Wv, Wo, bv);
    init_k<<<(NN * HH + 255) / 256, 256>>>();

    dim3 ggrid(6, (NN + 127) / 128);
    gemm_mma<<<ggrid, 256, SMEM_TOTAL>>>(bq, bk);

    edge_k<<<2048, 256>>>(ei, pos, Wg, bg);

    out_k<<<NN / 4, 256>>>(bo, out);
}